// round 1
// baseline (speedup 1.0000x reference)
#include <cuda_runtime.h>

#define VSIZE 100000
#define EDIM  128
#define DA    60
#define BN    4096
#define TN    8
#define CN    200
#define EPSV  1e-6f

// Scratch (device globals: no allocation allowed)
__device__ float g_cprojn[(size_t)VSIZE * DA];   // normalized c projections [V,60]
__device__ float g_tprojn[(size_t)BN * TN * DA]; // normalized t projections [B*T,60]
__device__ float g_Mt[EDIM * EDIM];              // Mt[k][e] = (R_w @ Bc_w)[e][k]
__device__ float g_bias2[EDIM];                  // R_w @ Bc_b + R_b

// ---------------------------------------------------------------------------
// Kernel 0: fuse M = R_w @ Bc_w (stored transposed) and bias2 = R_w@Bc_b + R_b
// grid 128 (e), block 128 (k)
// ---------------------------------------------------------------------------
__global__ void fuse_kernel(const float* __restrict__ Rw, const float* __restrict__ Bw,
                            const float* __restrict__ Bb, const float* __restrict__ Rb)
{
    int e = blockIdx.x;
    int k = threadIdx.x;
    __shared__ float sR[EDIM];
    __shared__ float sP[EDIM];
    sR[k] = Rw[e * EDIM + k];
    __syncthreads();
    float acc = 0.f;
#pragma unroll 8
    for (int j = 0; j < EDIM; j++)
        acc = fmaf(sR[j], Bw[j * EDIM + k], acc);
    g_Mt[k * EDIM + e] = acc;     // transposed store
    sP[k] = sR[k] * Bb[k];
    __syncthreads();
    if (k == 0) {
        float s = 0.f;
        for (int j = 0; j < EDIM; j++) s += sP[j];
        g_bias2[e] = s + Rb[e];
    }
}

// ---------------------------------------------------------------------------
// Kernel 1/2: project rows of an embedding table through W[DA,E] + bias, then
// normalize by eps-clamped L2 norm. 8 rows per 256-thread block.
// GATHER=false: all V rows of cvec -> g_cprojn.
// GATHER=true : rows tvec[titems[gr]]  -> g_tprojn.
// ---------------------------------------------------------------------------
template <bool GATHER>
__global__ __launch_bounds__(256)
void proj_kernel(const float* __restrict__ table,
                 const float* __restrict__ W,
                 const float* __restrict__ bias,
                 const int* __restrict__ idx)
{
    __shared__ __align__(16) float sW[DA][132];   // padded: conflict-free float4
    __shared__ __align__(16) float sRow[8][132];
    __shared__ float sOut[8][64];
    __shared__ float sB[64];

    float* out = GATHER ? g_tprojn : g_cprojn;
    int tid = threadIdx.x;

    for (int i = tid; i < DA * EDIM; i += 256)
        sW[i >> 7][i & 127] = W[i];
    if (tid < 64) sB[tid] = (tid < DA) ? bias[tid] : 0.f;

    {
        int r = tid >> 5, l = tid & 31;
        int gr = blockIdx.x * 8 + r;
        int rowv = GATHER ? idx[gr] : gr;
        float4 x = ((const float4*)(table + (size_t)rowv * EDIM))[l];
        ((float4*)&sRow[r][0])[l] = x;
    }
    __syncthreads();

    {
        int w = tid >> 5, l = tid & 31;
        int r = l >> 2;            // row 0..7
        int dq = l & 3;
        int d0 = w * 8 + dq;       // always < 60
        int d1 = d0 + 4;           // may be 60..63 (warp 7)
        const float4* xr  = (const float4*)&sRow[r][0];
        const float4* w0r = (const float4*)&sW[d0][0];
        const float4* w1r = (const float4*)&sW[d1 < DA ? d1 : 0][0];
        float a0 = 0.f, a1 = 0.f;
#pragma unroll
        for (int q = 0; q < 32; q++) {
            float4 xv = xr[q];
            float4 wa = w0r[q];
            float4 wb = w1r[q];
            a0 = fmaf(xv.x, wa.x, a0); a0 = fmaf(xv.y, wa.y, a0);
            a0 = fmaf(xv.z, wa.z, a0); a0 = fmaf(xv.w, wa.w, a0);
            a1 = fmaf(xv.x, wb.x, a1); a1 = fmaf(xv.y, wb.y, a1);
            a1 = fmaf(xv.z, wb.z, a1); a1 = fmaf(xv.w, wb.w, a1);
        }
        sOut[r][d0] = a0 + sB[d0];
        if (d1 < DA) sOut[r][d1] = a1 + sB[d1];
    }
    __syncthreads();

    {
        int w = tid >> 5, l = tid & 31;   // warp w handles row w
        float v0 = sOut[w][l];
        float v1 = (l + 32 < DA) ? sOut[w][l + 32] : 0.f;
        float ss = v0 * v0 + v1 * v1;
#pragma unroll
        for (int o = 16; o >= 1; o >>= 1)
            ss += __shfl_xor_sync(0xffffffffu, ss, o);
        float inv = 1.0f / fmaxf(sqrtf(ss), EPSV);
        int gr = blockIdx.x * 8 + w;
        float* op = out + (size_t)gr * DA;
        op[l] = v0 * inv;
        if (l + 32 < DA) op[l + 32] = v1 * inv;
    }
}

// ---------------------------------------------------------------------------
// Kernel 3: main. One CTA per batch row b. 256 threads.
//  P1: cos[t,c] = dot(tprojn[b,t], cprojn[cit]) (unit vectors), mask -> -1e30
//  P2: softmax over c per t
//  P3: s[t,e] = sum_c attn[t,c] * cvec[cit[c], e]   (u gathered in smem chunks)
//  P4: z[t,e] = sum_k s[t,k] * Mt[k,e] + bias2[e]
// ---------------------------------------------------------------------------
__global__ __launch_bounds__(256)
void main_kernel(const float* __restrict__ cvec,
                 const int* __restrict__ citems,
                 const int* __restrict__ maskp,
                 float* __restrict__ outp)
{
    __shared__ int   s_cit[CN];
    __shared__ int   s_mask[CN];
    __shared__ float s_tp[TN * DA];                    // 480
    __shared__ __align__(16) float s_aT[CN][8];        // cos/attn transposed
    __shared__ __align__(16) float s_u[16][EDIM];      // u staging chunk
    __shared__ __align__(16) float s_part[2][TN][EDIM];// partials / reused as zZ
    __shared__ __align__(16) float s_st[EDIM][8];      // s transposed [k][t]

    int b = blockIdx.x;
    int tid = threadIdx.x;
    int w = tid >> 5, l = tid & 31;

    if (tid < CN) {
        s_cit[tid]  = citems[b * CN + tid];
        s_mask[tid] = maskp[b * CN + tid];   // nonzero bits == masked (int32 or f32 bool)
    }
    for (int i = tid; i < TN * DA; i += 256)
        s_tp[i] = g_tprojn[(size_t)b * TN * DA + i];
    __syncthreads();

    // ---- Phase 1: cosine scores. warp w handles c = w*25 .. w*25+24 ----
    {
        float2 tp2[TN];
#pragma unroll
        for (int t = 0; t < TN; t++)
            tp2[t] = (l < 30) ? *(const float2*)&s_tp[t * DA + 2 * l]
                              : make_float2(0.f, 0.f);
        for (int k = 0; k < 25; k++) {
            int c = w * 25 + k;
            int tok = s_cit[c];
            float2 cp = (l < 30) ? ((const float2*)(g_cprojn + (size_t)tok * DA))[l]
                                 : make_float2(0.f, 0.f);
            float p[TN];
#pragma unroll
            for (int t = 0; t < TN; t++)
                p[t] = fmaf(cp.x, tp2[t].x, cp.y * tp2[t].y);
#pragma unroll
            for (int o = 16; o >= 1; o >>= 1) {
#pragma unroll
                for (int t = 0; t < TN; t++)
                    p[t] += __shfl_xor_sync(0xffffffffu, p[t], o);
            }
            if (l == 0) {
                bool m = (s_mask[c] != 0);
                float4 v0 = m ? make_float4(-1e30f, -1e30f, -1e30f, -1e30f)
                              : make_float4(p[0], p[1], p[2], p[3]);
                float4 v1 = m ? make_float4(-1e30f, -1e30f, -1e30f, -1e30f)
                              : make_float4(p[4], p[5], p[6], p[7]);
                ((float4*)&s_aT[c][0])[0] = v0;
                ((float4*)&s_aT[c][0])[1] = v1;
            }
        }
    }
    __syncthreads();

    // ---- Phase 2: softmax over c, warp w handles t = w ----
    {
        int t = w;
        float m = -1e30f;
        for (int c = l; c < CN; c += 32) m = fmaxf(m, s_aT[c][t]);
#pragma unroll
        for (int o = 16; o >= 1; o >>= 1)
            m = fmaxf(m, __shfl_xor_sync(0xffffffffu, m, o));
        float sum = 0.f;
        for (int c = l; c < CN; c += 32) {
            float ev = __expf(s_aT[c][t] - m);
            s_aT[c][t] = ev;
            sum += ev;
        }
#pragma unroll
        for (int o = 16; o >= 1; o >>= 1)
            sum += __shfl_xor_sync(0xffffffffu, sum, o);
        float inv = 1.0f / sum;
        for (int c = l; c < CN; c += 32) s_aT[c][t] *= inv;
    }
    __syncthreads();

    // ---- Phase 3: s = attn @ u ----
    int e  = tid & 127;
    int ch = tid >> 7;        // c-range half
    float acc[TN];
#pragma unroll
    for (int t = 0; t < TN; t++) acc[t] = 0.f;

    for (int cc = 0; cc < 13; cc++) {
        int c0 = cc * 16;
        int nrows = (c0 + 16 <= CN) ? 16 : (CN - c0);     // 16 or 8
        int nf4 = nrows * 32;
        for (int i = tid; i < nf4; i += 256) {
            int rr = i >> 5, li = i & 31;
            int tok = s_cit[c0 + rr];
            ((float4*)s_u)[i] = ((const float4*)(cvec + (size_t)tok * EDIM))[li];
        }
        __syncthreads();
        int half = nrows >> 1;
        int rbase = ch * half;
        for (int j = 0; j < half; j++) {
            int rr = rbase + j;
            int c = c0 + rr;
            float uv = s_u[rr][e];
            float4 a0 = ((const float4*)&s_aT[c][0])[0];
            float4 a1 = ((const float4*)&s_aT[c][0])[1];
            acc[0] = fmaf(a0.x, uv, acc[0]);
            acc[1] = fmaf(a0.y, uv, acc[1]);
            acc[2] = fmaf(a0.z, uv, acc[2]);
            acc[3] = fmaf(a0.w, uv, acc[3]);
            acc[4] = fmaf(a1.x, uv, acc[4]);
            acc[5] = fmaf(a1.y, uv, acc[5]);
            acc[6] = fmaf(a1.z, uv, acc[6]);
            acc[7] = fmaf(a1.w, uv, acc[7]);
        }
        __syncthreads();
    }
#pragma unroll
    for (int t = 0; t < TN; t++) s_part[ch][t][e] = acc[t];
    __syncthreads();

    if (tid < EDIM) {
#pragma unroll
        for (int t = 0; t < TN; t++)
            s_st[tid][t] = s_part[0][t][tid] + s_part[1][t][tid];
    }
    __syncthreads();

    // ---- Phase 4: z = s @ Mt + bias2 (k-range split by ch) ----
    float z[TN];
#pragma unroll
    for (int t = 0; t < TN; t++) z[t] = 0.f;
    {
        int k0 = ch * 64;
#pragma unroll 4
        for (int k = k0; k < k0 + 64; k++) {
            float mv = g_Mt[k * EDIM + e];
            float4 sa = ((const float4*)&s_st[k][0])[0];
            float4 sb = ((const float4*)&s_st[k][0])[1];
            z[0] = fmaf(sa.x, mv, z[0]);
            z[1] = fmaf(sa.y, mv, z[1]);
            z[2] = fmaf(sa.z, mv, z[2]);
            z[3] = fmaf(sa.w, mv, z[3]);
            z[4] = fmaf(sb.x, mv, z[4]);
            z[5] = fmaf(sb.y, mv, z[5]);
            z[6] = fmaf(sb.z, mv, z[6]);
            z[7] = fmaf(sb.w, mv, z[7]);
        }
    }
#pragma unroll
    for (int t = 0; t < TN; t++) s_part[ch][t][e] = z[t];   // reuse as zZ
    __syncthreads();

#pragma unroll
    for (int q = 0; q < 4; q++) {
        int o = tid + 256 * q;         // 0..1023 over (t,e)
        int t = o >> 7, ee = o & 127;
        outp[(size_t)b * (TN * EDIM) + o] =
            s_part[0][t][ee] + s_part[1][t][ee] + g_bias2[ee];
    }
}

// ---------------------------------------------------------------------------
extern "C" void kernel_launch(void* const* d_in, const int* in_sizes, int n_in,
                              void* d_out, int out_size)
{
    const float* cvec  = (const float*)d_in[1];
    const float* Ac_w  = (const float*)d_in[2];
    const float* Ac_b  = (const float*)d_in[3];
    const float* tvec  = (const float*)d_in[0];
    const float* At_w  = (const float*)d_in[4];
    const float* At_b  = (const float*)d_in[5];
    const float* Bc_w  = (const float*)d_in[6];
    const float* Bc_b  = (const float*)d_in[7];
    const float* R_w   = (const float*)d_in[8];
    const float* R_b   = (const float*)d_in[9];
    const int*   titems = (const int*)d_in[10];
    const int*   citems = (const int*)d_in[11];
    const int*   maskp  = (const int*)d_in[12];

    fuse_kernel<<<EDIM, EDIM>>>(R_w, Bc_w, Bc_b, R_b);
    proj_kernel<false><<<VSIZE / 8, 256>>>(cvec, Ac_w, Ac_b, nullptr);
    proj_kernel<true><<<(BN * TN) / 8, 256>>>(tvec, At_w, At_b, titems);
    main_kernel<<<BN, 256>>>(cvec, citems, maskp, (float*)d_out);
}